// round 1
// baseline (speedup 1.0000x reference)
#include <cuda_runtime.h>
#include <cstdint>

// Problem constants
#define BB   8
#define CC   256
#define HH   64
#define WW   64
#define OO   256
#define K2   9
#define KDIM (CC * K2)          // 2304
#define PIXI (HH * WW)          // 4096 pixels per image
#define NPIX (BB * PIXI)        // 32768

// Tiling
#define BM 128
#define BN 128
#define BK 16
#define NTHREADS 256

// Shared memory layout (dynamic, 60 KB total):
//   float4 cw [K2][BN]   : bilinear corner weights (validity folded in)  18432 B
//   int4   ci [K2][BN]   : clamped corner flat indices within a plane    18432 B
//   float2 As2[BK][BM]   : weight tile, each value duplicated (a,a)      16384 B
//   float  Bs [BK][BN]   : sampled tile                                   8192 B
#define SMEM_CW   0
#define SMEM_CI   (SMEM_CW + K2 * BN * 16)
#define SMEM_AS   (SMEM_CI + K2 * BN * 16)
#define SMEM_BS   (SMEM_AS + BK * BM * 8)
#define SMEM_TOTAL (SMEM_BS + BK * BN * 4)   // 61440

__device__ __forceinline__ void ffma2(float2& d, float2 a, float2 b) {
    unsigned long long ud = *reinterpret_cast<unsigned long long*>(&d);
    unsigned long long ua = *reinterpret_cast<unsigned long long*>(&a);
    unsigned long long ub = *reinterpret_cast<unsigned long long*>(&b);
    asm("fma.rn.f32x2 %0, %1, %2, %0;" : "+l"(ud) : "l"(ua), "l"(ub));
    d = *reinterpret_cast<float2*>(&ud);
}

__global__ void __launch_bounds__(NTHREADS)
dfconv_kernel(const float* __restrict__ x,
              const float* __restrict__ offset,
              const float* __restrict__ weight,
              float* __restrict__ out)
{
    extern __shared__ char smem[];
    float4* cw  = reinterpret_cast<float4*>(smem + SMEM_CW);
    int4*   ci  = reinterpret_cast<int4*>(smem + SMEM_CI);
    float2* As2 = reinterpret_cast<float2*>(smem + SMEM_AS);
    float*  Bs  = reinterpret_cast<float*>(smem + SMEM_BS);

    const int tid   = threadIdx.x;
    const int o0    = blockIdx.x * BM;
    const int pix0  = blockIdx.y * BN;        // global flattened pixel base
    const int b     = pix0 / PIXI;            // BN divides PIXI -> whole block same batch
    const int pimg0 = pix0 - b * PIXI;        // pixel index within image

    // ---------------- prologue: bilinear coefficients for 9 taps x 128 pixels ----
    for (int t = tid; t < K2 * BN; t += NTHREADS) {
        const int k = t / BN;
        const int p = t - k * BN;
        const int pimg = pimg0 + p;
        const int h = pimg >> 6;
        const int w = pimg & 63;
        const int ky = k / 3;
        const int kx = k - ky * 3;
        const float dy = offset[((b * 18 + k * 2 + 0) * PIXI) + pimg];
        const float dx = offset[((b * 18 + k * 2 + 1) * PIXI) + pimg];
        const float py = (float)(h - 1 + ky) + dy;   // PAD=1, DIL=1
        const float px = (float)(w - 1 + kx) + dx;
        const float y0f = floorf(py);
        const float x0f = floorf(px);
        const float fy = py - y0f;
        const float fx = px - x0f;
        const int y0 = (int)y0f;
        const int x0 = (int)x0f;

        const bool vy0 = (y0     >= 0) && (y0     <= HH - 1);
        const bool vy1 = (y0 + 1 >= 0) && (y0 + 1 <= HH - 1);
        const bool vx0 = (x0     >= 0) && (x0     <= WW - 1);
        const bool vx1 = (x0 + 1 >= 0) && (x0 + 1 <= WW - 1);

        float4 wv;
        wv.x = (vy0 && vx0) ? (1.f - fy) * (1.f - fx) : 0.f;
        wv.y = (vy0 && vx1) ? (1.f - fy) * fx         : 0.f;
        wv.z = (vy1 && vx0) ? fy * (1.f - fx)         : 0.f;
        wv.w = (vy1 && vx1) ? fy * fx                 : 0.f;

        const int yc0 = min(max(y0,     0), HH - 1);
        const int yc1 = min(max(y0 + 1, 0), HH - 1);
        const int xc0 = min(max(x0,     0), WW - 1);
        const int xc1 = min(max(x0 + 1, 0), WW - 1);
        int4 iv;
        iv.x = yc0 * WW + xc0;
        iv.y = yc0 * WW + xc1;
        iv.z = yc1 * WW + xc0;
        iv.w = yc1 * WW + xc1;

        cw[t] = wv;
        ci[t] = iv;
    }
    __syncthreads();

    // ---------------- mainloop: fused gather + GEMM ------------------------------
    const int ty = tid >> 4;   // 0..15 -> output-channel group (8 each)
    const int tx = tid & 15;   // 0..15 -> pixel group (8 each, as 4 float2 pairs)

    float2 acc[8][4];
    #pragma unroll
    for (int i = 0; i < 8; i++)
        #pragma unroll
        for (int j = 0; j < 4; j++)
            acc[i][j] = make_float2(0.f, 0.f);

    const float* xb = x + (size_t)b * CC * PIXI;

    for (int kc = 0; kc < KDIM; kc += BK) {
        // A tile: weight[o0+row][kc..kc+16), stored duplicated (a,a)
        {
            const int row  = tid >> 1;
            const int colg = (tid & 1) * 8;
            const float* wrow = weight + (size_t)(o0 + row) * KDIM + kc + colg;
            const float4 v0 = *reinterpret_cast<const float4*>(wrow);
            const float4 v1 = *reinterpret_cast<const float4*>(wrow + 4);
            As2[(colg + 0) * BM + row] = make_float2(v0.x, v0.x);
            As2[(colg + 1) * BM + row] = make_float2(v0.y, v0.y);
            As2[(colg + 2) * BM + row] = make_float2(v0.z, v0.z);
            As2[(colg + 3) * BM + row] = make_float2(v0.w, v0.w);
            As2[(colg + 4) * BM + row] = make_float2(v1.x, v1.x);
            As2[(colg + 5) * BM + row] = make_float2(v1.y, v1.y);
            As2[(colg + 6) * BM + row] = make_float2(v1.z, v1.z);
            As2[(colg + 7) * BM + row] = make_float2(v1.w, v1.w);
        }

        // B tile: gather 16 (c,k) rows x 128 pixels
        #pragma unroll
        for (int it = 0; it < (BK * BN) / NTHREADS; ++it) {   // 8 samples/thread
            const int t  = tid + it * NTHREADS;
            const int kk = t >> 7;           // /BN
            const int p  = t & 127;
            const int kidx = kc + kk;
            const int c = kidx / 9;
            const int k = kidx - c * 9;
            const float4 wv = cw[k * BN + p];
            const int4   iv = ci[k * BN + p];
            const float* plane = xb + (size_t)c * PIXI;
            const float s = wv.x * plane[iv.x] + wv.y * plane[iv.y]
                          + wv.z * plane[iv.z] + wv.w * plane[iv.w];
            Bs[kk * BN + p] = s;
        }
        __syncthreads();

        // compute 128x128 += 128x16 * 16x128 with packed f32x2 FMA
        #pragma unroll
        for (int kk = 0; kk < BK; ++kk) {
            float4 av[4];
            const float4* ap = reinterpret_cast<const float4*>(As2 + kk * BM + ty * 8);
            av[0] = ap[0]; av[1] = ap[1]; av[2] = ap[2]; av[3] = ap[3];
            const float2* a = reinterpret_cast<const float2*>(av);  // 8 (a,a) pairs

            float4 bvv[2];
            const float4* bp4 = reinterpret_cast<const float4*>(Bs + kk * BN + tx * 8);
            bvv[0] = bp4[0]; bvv[1] = bp4[1];
            const float2* bp = reinterpret_cast<const float2*>(bvv); // 4 pixel pairs

            #pragma unroll
            for (int i = 0; i < 8; i++)
                #pragma unroll
                for (int j = 0; j < 4; j++)
                    ffma2(acc[i][j], a[i], bp[j]);
        }
        __syncthreads();
    }

    // ---------------- epilogue ----------------------------------------------------
    #pragma unroll
    for (int i = 0; i < 8; i++) {
        const int o = o0 + ty * 8 + i;
        float* orow = out + ((size_t)(b * OO + o)) * PIXI + pimg0 + tx * 8;
        float4 s0, s1;
        s0.x = acc[i][0].x; s0.y = acc[i][0].y; s0.z = acc[i][1].x; s0.w = acc[i][1].y;
        s1.x = acc[i][2].x; s1.y = acc[i][2].y; s1.z = acc[i][3].x; s1.w = acc[i][3].y;
        *reinterpret_cast<float4*>(orow)     = s0;
        *reinterpret_cast<float4*>(orow + 4) = s1;
    }
}

extern "C" void kernel_launch(void* const* d_in, const int* in_sizes, int n_in,
                              void* d_out, int out_size)
{
    const float* x      = (const float*)d_in[0];
    const float* offset = (const float*)d_in[1];
    const float* weight = (const float*)d_in[2];
    float* out          = (float*)d_out;

    cudaFuncSetAttribute(dfconv_kernel,
                         cudaFuncAttributeMaxDynamicSharedMemorySize, SMEM_TOTAL);

    dim3 grid(OO / BM, NPIX / BN);   // (2, 256)
    dfconv_kernel<<<grid, NTHREADS, SMEM_TOTAL>>>(x, offset, weight, out);
}

// round 3
// speedup vs baseline: 8.7355x; 8.7355x over previous
#include <cuda_runtime.h>
#include <cstdint>

// ---------------------------------------------------------------- problem dims
#define BB   8
#define CC   256
#define HH   64
#define WW   64
#define OO   256
#define TAPS 9
#define KTOT (CC * TAPS)        // 2304
#define PIXI (HH * WW)          // 4096
#define TILE_P 128              // pixels per CTA
#define BKC  32                 // channels per K-chunk
#define NCHUNK (TAPS * (CC / BKC))  // 72
#define NTH  512

// ---------------------------------------------------------------- scratch
__device__ float g_x_nhwc[(size_t)BB * PIXI * CC];   // [b][pix][c]
__device__ float g_wtf[(size_t)OO * KTOT];           // fragment-major weights (tf32 bits)

// ---------------------------------------------------------------- smem layout
// A: 2 bufs x [4 ksteps][16 otiles][32 lanes][4 floats] = 2 x 32768
// B: 2 bufs x [4 ksteps][16 ntiles][32 lanes][2 floats] = 2 x 16384
#define SM_A   0
#define SM_B   (SM_A + 2 * 32768)          // 65536
#define SM_CW  (SM_B + 2 * 16384)          // 98304
#define SM_CI  (SM_CW + TAPS * TILE_P * 16)  // +18432 = 116736
#define SMEM_SZ (SM_CI + TAPS * TILE_P * 8)  // +9216  = 125952

// ---------------------------------------------------------------- helpers
__device__ __forceinline__ uint32_t smem_u32(const void* p) {
    uint32_t a;
    asm("{ .reg .u64 t; cvta.to.shared.u64 t, %1; cvt.u32.u64 %0, t; }" : "=r"(a) : "l"(p));
    return a;
}
__device__ __forceinline__ unsigned long long dup2(float a) {
    unsigned long long r;
    asm("mov.b64 %0, {%1, %1};" : "=l"(r) : "f"(a));
    return r;
}
__device__ __forceinline__ unsigned long long mul2(unsigned long long a, unsigned long long b) {
    unsigned long long d;
    asm("mul.rn.f32x2 %0, %1, %2;" : "=l"(d) : "l"(a), "l"(b));
    return d;
}
__device__ __forceinline__ void fma2(unsigned long long& d, unsigned long long a,
                                     unsigned long long b) {
    asm("fma.rn.f32x2 %0, %1, %2, %0;" : "+l"(d) : "l"(a), "l"(b));
}
__device__ __forceinline__ uint32_t to_tf32(float f) {
    uint32_t u;
    asm("cvt.rna.tf32.f32 %0, %1;" : "=r"(u) : "f"(f));
    return u;
}
#define CP_ASYNC16(sa, ga) \
    asm volatile("cp.async.cg.shared.global [%0], [%1], 16;" :: "r"(sa), "l"(ga))
#define CP_COMMIT() asm volatile("cp.async.commit_group;" ::: "memory")
#define CP_WAIT0()  asm volatile("cp.async.wait_group 0;" ::: "memory")

__device__ __forceinline__ void mma_tf32(float* d, const uint32_t* a, const uint32_t* b) {
    asm volatile(
        "mma.sync.aligned.m16n8k8.row.col.f32.tf32.tf32.f32 "
        "{%0,%1,%2,%3}, {%4,%5,%6,%7}, {%8,%9}, {%0,%1,%2,%3};"
        : "+f"(d[0]), "+f"(d[1]), "+f"(d[2]), "+f"(d[3])
        : "r"(a[0]), "r"(a[1]), "r"(a[2]), "r"(a[3]), "r"(b[0]), "r"(b[1]));
}

// ---------------------------------------------------------------- transforms
__global__ void xpose_kernel(const float* __restrict__ x) {
    __shared__ float tile[32][33];
    const int p0 = blockIdx.x * 32;
    const int c0 = blockIdx.y * 32;
    const int tx = threadIdx.x, ty = threadIdx.y;
    const int b = p0 >> 12;
    const int pimg = p0 - (b << 12);
    #pragma unroll
    for (int i = 0; i < 4; i++) {
        const int c = c0 + ty + i * 8;
        tile[tx][ty + i * 8] = x[((size_t)(b * CC + c)) * PIXI + pimg + tx];
    }
    __syncthreads();
    #pragma unroll
    for (int i = 0; i < 4; i++) {
        const int pl = ty + i * 8;
        g_x_nhwc[((size_t)(p0 + pl)) * CC + c0 + tx] = tile[pl][tx];
    }
}

// weight -> A-fragment-major (m16n8k8 tf32), pre-converted with cvt.rna.tf32
// layout: [ck=0..71][s=0..3][otile=0..15][lane=0..31][reg=0..3]
__global__ void wposef_kernel(const float* __restrict__ w) {
    const int i = blockIdx.x * 256 + threadIdx.x;       // < OO*KTOT
    const int reg   = i & 3;
    const int lane  = (i >> 2) & 31;
    const int otile = (i >> 7) & 15;
    const int s     = (i >> 11) & 3;
    const int ck    = i >> 13;
    const int o  = otile * 16 + (lane >> 2) + (reg & 1) * 8;
    const int k8 = (lane & 3) + (reg >> 1) * 4;
    const int c  = (ck & 7) * 32 + s * 8 + k8;
    const int tap = ck >> 3;
    const float v = w[((size_t)(o * CC + c)) * TAPS + tap];
    g_wtf[i] = __uint_as_float(to_tf32(v));
}

// ---------------------------------------------------------------- main kernel
__global__ void __launch_bounds__(NTH, 1)
dfconv_main(const float* __restrict__ offset, float* __restrict__ out) {
    extern __shared__ char smem[];
    const int tid  = threadIdx.x;
    const int wid  = tid >> 5;
    const int lane = tid & 31;

    const int b     = blockIdx.x >> 5;
    const int pimg0 = (blockIdx.x & 31) * TILE_P;

    float4*  cw = reinterpret_cast<float4*>(smem + SM_CW);
    ushort4* ci = reinterpret_cast<ushort4*>(smem + SM_CI);

    // ---- bilinear coefficients: 9 taps x 128 pixels
    for (int t = tid; t < TAPS * TILE_P; t += NTH) {
        const int k = t >> 7;
        const int p = t & 127;
        const int pimg = pimg0 + p;
        const int h = pimg >> 6;
        const int w = pimg & 63;
        const int ky = k / 3;
        const int kx = k - ky * 3;
        const float dy = offset[((size_t)(b * 18 + k * 2 + 0)) * PIXI + pimg];
        const float dx = offset[((size_t)(b * 18 + k * 2 + 1)) * PIXI + pimg];
        const float py = (float)(h - 1 + ky) + dy;
        const float px = (float)(w - 1 + kx) + dx;
        const float y0f = floorf(py);
        const float x0f = floorf(px);
        const float fy = py - y0f;
        const float fx = px - x0f;
        const int y0 = (int)y0f;
        const int x0 = (int)x0f;
        const bool vy0 = (y0 >= 0) && (y0 <= HH - 1);
        const bool vy1 = (y0 + 1 >= 0) && (y0 + 1 <= HH - 1);
        const bool vx0 = (x0 >= 0) && (x0 <= WW - 1);
        const bool vx1 = (x0 + 1 >= 0) && (x0 + 1 <= WW - 1);
        float4 wv;
        wv.x = (vy0 && vx0) ? (1.f - fy) * (1.f - fx) : 0.f;
        wv.y = (vy0 && vx1) ? (1.f - fy) * fx         : 0.f;
        wv.z = (vy1 && vx0) ? fy * (1.f - fx)         : 0.f;
        wv.w = (vy1 && vx1) ? fy * fx                 : 0.f;
        const int yc0 = min(max(y0,     0), HH - 1);
        const int yc1 = min(max(y0 + 1, 0), HH - 1);
        const int xc0 = min(max(x0,     0), WW - 1);
        const int xc1 = min(max(x0 + 1, 0), WW - 1);
        ushort4 iv;
        iv.x = (unsigned short)(yc0 * WW + xc0);
        iv.y = (unsigned short)(yc0 * WW + xc1);
        iv.z = (unsigned short)(yc1 * WW + xc0);
        iv.w = (unsigned short)(yc1 * WW + xc1);
        cw[t] = wv;
        ci[t] = iv;
    }

    const float* xb = g_x_nhwc + (size_t)b * PIXI * CC;
    const int seg = tid & 7;                 // channel group of 4
    const int prow = tid >> 3;               // 0..63 (pixel within 64-group)

    // gather one chunk into B buffer `bufsel`
    auto gather = [&](int ck, int bufsel) {
        const int tap = ck >> 3;
        const int c0  = (ck & 7) * BKC;
        float* bb = reinterpret_cast<float*>(smem + SM_B + bufsel * 16384);
        const float* xc = xb + c0 + seg * 4;
        const int s16 = (seg >> 1) * 16;
        const int rsel = seg & 1;
        #pragma unroll
        for (int it = 0; it < 2; it++) {
            const int p = it * 64 + prow;
            const float4  wv = cw[tap * TILE_P + p];
            const ushort4 iv = ci[tap * TILE_P + p];
            const float4 v00 = *reinterpret_cast<const float4*>(xc + (int)iv.x * CC);
            const float4 v01 = *reinterpret_cast<const float4*>(xc + (int)iv.y * CC);
            const float4 v10 = *reinterpret_cast<const float4*>(xc + (int)iv.z * CC);
            const float4 v11 = *reinterpret_cast<const float4*>(xc + (int)iv.w * CC);
            const unsigned long long wx = dup2(wv.x), wy = dup2(wv.y);
            const unsigned long long wz = dup2(wv.z), ww2 = dup2(wv.w);
            const unsigned long long* a0 = reinterpret_cast<const unsigned long long*>(&v00);
            const unsigned long long* a1 = reinterpret_cast<const unsigned long long*>(&v01);
            const unsigned long long* a2 = reinterpret_cast<const unsigned long long*>(&v10);
            const unsigned long long* a3 = reinterpret_cast<const unsigned long long*>(&v11);
            unsigned long long s0 = mul2(wx, a0[0]);
            fma2(s0, wy, a1[0]); fma2(s0, wz, a2[0]); fma2(s0, ww2, a3[0]);
            unsigned long long s1 = mul2(wx, a0[1]);
            fma2(s1, wy, a1[1]); fma2(s1, wz, a2[1]); fma2(s1, ww2, a3[1]);
            const float* sf = reinterpret_cast<const float*>(&s0);
            const float* sg = reinterpret_cast<const float*>(&s1);
            // B fragment address: ((s*16 + p>>3)*32 + (p&7)*4 + j)*2 + reg
            const int base = ((s16 + (p >> 3)) * 32 + (p & 7) * 4) * 2 + rsel;
            bb[base + 0] = __uint_as_float(to_tf32(sf[0]));
            bb[base + 2] = __uint_as_float(to_tf32(sf[1]));
            bb[base + 4] = __uint_as_float(to_tf32(sg[0]));
            bb[base + 6] = __uint_as_float(to_tf32(sg[1]));
        }
    };

    // A chunk prefetch via cp.async: 32KB, 512 threads x 4 x 16B
    auto a_prefetch = [&](int ck, int bufsel) {
        const float* src = g_wtf + (size_t)ck * 8192 + tid * 4;
        const uint32_t dst = smem_u32(smem + SM_A + bufsel * 32768) + tid * 16;
        #pragma unroll
        for (int i = 0; i < 4; i++)
            CP_ASYNC16(dst + i * 8192, src + i * 2048);
        CP_COMMIT();
    };

    // ---- prologue
    a_prefetch(0, 0);
    CP_WAIT0();
    __syncthreads();          // coefficients ready before gather
    gather(0, 0);
    __syncthreads();

    const int warp_m = wid >> 2;   // 0..3 -> 64 output rows
    const int warp_n = wid & 3;    // 0..3 -> 32 pixels

    float acc[4][4][4];
    #pragma unroll
    for (int mf = 0; mf < 4; mf++)
        #pragma unroll
        for (int nf = 0; nf < 4; nf++)
            #pragma unroll
            for (int r = 0; r < 4; r++)
                acc[mf][nf][r] = 0.f;

    for (int ck = 0; ck < NCHUNK; ck++) {
        const int buf = ck & 1;
        if (ck + 1 < NCHUNK) a_prefetch(ck + 1, buf ^ 1);

        const uint32_t* Af = reinterpret_cast<const uint32_t*>(smem + SM_A + buf * 32768);
        const uint32_t* Bf = reinterpret_cast<const uint32_t*>(smem + SM_B + buf * 16384);

        #pragma unroll
        for (int s = 0; s < 4; s++) {
            uint32_t a[4][4];
            uint32_t bq[4][2];
            #pragma unroll
            for (int mf = 0; mf < 4; mf++) {
                const uint4 v = reinterpret_cast<const uint4*>(Af)[(s * 16 + warp_m * 4 + mf) * 32 + lane];
                a[mf][0] = v.x; a[mf][1] = v.y; a[mf][2] = v.z; a[mf][3] = v.w;
            }
            #pragma unroll
            for (int nf = 0; nf < 4; nf++) {
                const uint2 v = reinterpret_cast<const uint2*>(Bf)[(s * 16 + warp_n * 4 + nf) * 32 + lane];
                bq[nf][0] = v.x; bq[nf][1] = v.y;
            }
            #pragma unroll
            for (int mf = 0; mf < 4; mf++)
                #pragma unroll
                for (int nf = 0; nf < 4; nf++)
                    mma_tf32(acc[mf][nf], a[mf], bq[nf]);
        }

        if (ck + 1 < NCHUNK) gather(ck + 1, buf ^ 1);
        CP_WAIT0();
        __syncthreads();
    }

    // ---- epilogue
    #pragma unroll
    for (int mf = 0; mf < 4; mf++) {
        const int o = warp_m * 64 + mf * 16 + (lane >> 2);
        float* r0 = out + ((size_t)(b * OO + o)) * PIXI + pimg0 + warp_n * 32 + (lane & 3) * 2;
        float* r1 = r0 + 8 * PIXI;
        #pragma unroll
        for (int nf = 0; nf < 4; nf++) {
            float2 v0 = make_float2(acc[mf][nf][0], acc[mf][nf][1]);
            float2 v1 = make_float2(acc[mf][nf][2], acc[mf][nf][3]);
            *reinterpret_cast<float2*>(r0 + nf * 8) = v0;
            *reinterpret_cast<float2*>(r1 + nf * 8) = v1;
        }
    }
}

// ---------------------------------------------------------------- launcher
extern "C" void kernel_launch(void* const* d_in, const int* in_sizes, int n_in,
                              void* d_out, int out_size) {
    const float* x      = (const float*)d_in[0];
    const float* offset = (const float*)d_in[1];
    const float* weight = (const float*)d_in[2];
    float* out          = (float*)d_out;

    cudaFuncSetAttribute(dfconv_main,
                         cudaFuncAttributeMaxDynamicSharedMemorySize, SMEM_SZ);

    dim3 xg((BB * PIXI) / 32, CC / 32);
    xpose_kernel<<<xg, dim3(32, 8)>>>(x);
    wposef_kernel<<<(OO * KTOT) / 256, 256>>>(weight);
    dfconv_main<<<BB * (PIXI / TILE_P), NTH, SMEM_SZ>>>(offset, out);
}